// round 6
// baseline (speedup 1.0000x reference)
#include <cuda_runtime.h>
#include <math.h>

// out[b,k] = exp(-beta_k * max(||x_b||^2 + ||c_k||^2 - 2 x_b.c_k, 0))
// B=16384, K=4096, D=1024, fp32.
//
// fp32 exp(-t) == exactly 0.0f for t > ~104. Cauchy-Schwarz: d2 >= (||x_b||-||c_k||)^2.
// Per-column interval [lo_k, hi_k] of ||x|| for which the element is NOT provably
// zero; global interval over k. Structure (decoupled single-purpose kernels):
//   1) norms      : row norms of centers and x (+ per-column intervals)
//   2) glob       : global interval reduce
//   3) zerofill   : pure streaming float4 zero-store over the whole output
//   4) fixup      : one block per row; early-exit if row provably zero, else
//                   recompute the row exactly (interval test + fp32 dot + expf)
// Correct for arbitrary inputs; on this data fixup exits almost everywhere and
// runtime ~= zerofill (output-store roofline).

#define B_ROWS 16384
#define K_COLS 4096
#define D_DIM  1024
#define THRESH 106.0f

#define ZBLOCKS 2048
#define ZITER   32   // ZBLOCKS*256*ZITER == B*K/4 exactly

__device__ float g_x2[B_ROWS];
__device__ float g_rx[B_ROWS];
__device__ float g_c2[K_COLS];
__device__ float g_lo[K_COLS];
__device__ float g_hi[K_COLS];
__device__ float g_glo;
__device__ float g_ghi;

// ---------------------------------------------------------------------------
// Kernel 1: row norms. Rows [0,K): centers -> c2, lo, hi. Rows [K,K+B): x -> x2, rx.
// ---------------------------------------------------------------------------
__global__ void __launch_bounds__(256) norms_kernel(const float* __restrict__ x,
                                                    const float* __restrict__ c,
                                                    const float* __restrict__ betas) {
    const int row = blockIdx.x;
    const bool is_center = (row < K_COLS);
    const float* src = is_center ? (c + (size_t)row * D_DIM)
                                 : (x + (size_t)(row - K_COLS) * D_DIM);
    const int tid = threadIdx.x;
    float4 a = reinterpret_cast<const float4*>(src)[tid];
    float s = a.x * a.x + a.y * a.y + a.z * a.z + a.w * a.w;
    #pragma unroll
    for (int o = 16; o > 0; o >>= 1)
        s += __shfl_xor_sync(0xffffffffu, s, o);
    __shared__ float ws[8];
    if ((tid & 31) == 0) ws[tid >> 5] = s;
    __syncthreads();
    if (tid == 0) {
        float t = 0.f;
        #pragma unroll
        for (int i = 0; i < 8; i++) t += ws[i];
        if (is_center) {
            g_c2[row] = t;
            const float beta = betas[row];
            const float sk = sqrtf(t);
            float lo = -INFINITY, hi = INFINITY;
            if (beta > 0.0f && isfinite(sk)) {
                const float rk = sqrtf(THRESH / beta);
                if (isfinite(rk)) { lo = sk - rk; hi = sk + rk; }
            }
            if (!(lo == lo)) lo = -INFINITY;   // NaN -> always-fallback interval
            if (!(hi == hi)) hi =  INFINITY;
            g_lo[row] = lo;
            g_hi[row] = hi;
        } else {
            g_x2[row - K_COLS] = t;
            g_rx[row - K_COLS] = sqrtf(t);
        }
    }
}

// ---------------------------------------------------------------------------
// Kernel 2: global interval reduce.
// ---------------------------------------------------------------------------
__global__ void __launch_bounds__(256) glob_kernel() {
    __shared__ float slo[256], shi[256];
    float lo = INFINITY, hi = -INFINITY;
    for (int k = threadIdx.x; k < K_COLS; k += 256) {
        lo = fminf(lo, g_lo[k]);
        hi = fmaxf(hi, g_hi[k]);
    }
    slo[threadIdx.x] = lo;
    shi[threadIdx.x] = hi;
    __syncthreads();
    for (int s2 = 128; s2 > 0; s2 >>= 1) {
        if (threadIdx.x < s2) {
            slo[threadIdx.x] = fminf(slo[threadIdx.x], slo[threadIdx.x + s2]);
            shi[threadIdx.x] = fmaxf(shi[threadIdx.x], shi[threadIdx.x + s2]);
        }
        __syncthreads();
    }
    if (threadIdx.x == 0) { g_glo = slo[0]; g_ghi = shi[0]; }
}

// ---------------------------------------------------------------------------
// Kernel 3: pure streaming zero-fill of the full output. No branches, no smem,
// no barriers. Streaming stores (evict-first) to bypass L2 pollution.
// ---------------------------------------------------------------------------
__global__ void __launch_bounds__(256) zerofill(float4* __restrict__ out) {
    const float4 z = make_float4(0.f, 0.f, 0.f, 0.f);
    const size_t base   = (size_t)blockIdx.x * 256 + threadIdx.x;
    const size_t stride = (size_t)ZBLOCKS * 256;
    #pragma unroll 8
    for (int s = 0; s < ZITER; s++)
        __stcs(&out[base + (size_t)s * stride], z);
}

// ---------------------------------------------------------------------------
// Kernel 4: fixup. One block per row. Early-exit when the row is provably
// zero (the overwhelmingly common case). Otherwise recompute the full row
// exactly and overwrite it.
// ---------------------------------------------------------------------------
__global__ void __launch_bounds__(256) fixup(const float* __restrict__ x,
                                             const float* __restrict__ c,
                                             const float* __restrict__ betas,
                                             float* __restrict__ out) {
    const int b = blockIdx.x;
    const float t = g_rx[b];
    // provably-zero row: every column's interval misses t
    if (t < g_glo || t > g_ghi) return;   // NaN t falls through to exact path

    const int tid = threadIdx.x;
    __shared__ float xs[D_DIM];
    reinterpret_cast<float4*>(xs)[tid] =
        reinterpret_cast<const float4*>(x + (size_t)b * D_DIM)[tid];
    __syncthreads();
    const float sx = g_x2[b];
    float4* __restrict__ orow = reinterpret_cast<float4*>(out + (size_t)b * K_COLS);

    #pragma unroll
    for (int j = 0; j < 4; j++) {
        const int kq = tid + 256 * j;                       // float4 column group
        const float4 lo4 = reinterpret_cast<const float4*>(g_lo)[kq];
        const float4 hi4 = reinterpret_cast<const float4*>(g_hi)[kq];
        const float4 c24 = reinterpret_cast<const float4*>(g_c2)[kq];
        const float4 bt4 = reinterpret_cast<const float4*>(betas)[kq];
        const float lo_a[4] = {lo4.x, lo4.y, lo4.z, lo4.w};
        const float hi_a[4] = {hi4.x, hi4.y, hi4.z, hi4.w};
        const float c2_a[4] = {c24.x, c24.y, c24.z, c24.w};
        const float bt_a[4] = {bt4.x, bt4.y, bt4.z, bt4.w};
        float o[4];
        #pragma unroll
        for (int q = 0; q < 4; q++) {
            if (t < lo_a[q] || t > hi_a[q]) {
                o[q] = 0.0f;                                // provably underflows
            } else {
                const float* __restrict__ cr = c + (size_t)(kq * 4 + q) * D_DIM;
                float dot = 0.f;
                #pragma unroll 8
                for (int i = 0; i < D_DIM; i++) dot = fmaf(xs[i], cr[i], dot);
                const float d2 = fmaxf(sx + c2_a[q] - 2.0f * dot, 0.0f);
                o[q] = expf(-bt_a[q] * d2);
            }
        }
        orow[kq] = make_float4(o[0], o[1], o[2], o[3]);
    }
}

// ---------------------------------------------------------------------------
extern "C" void kernel_launch(void* const* d_in, const int* in_sizes, int n_in,
                              void* d_out, int out_size) {
    const float* x     = (const float*)d_in[0];
    const float* cent  = (const float*)d_in[1];
    const float* betas = (const float*)d_in[2];
    float* out = (float*)d_out;

    norms_kernel<<<K_COLS + B_ROWS, 256>>>(x, cent, betas);
    glob_kernel<<<1, 256>>>();
    zerofill<<<ZBLOCKS, 256>>>(reinterpret_cast<float4*>(out));
    fixup<<<B_ROWS, 256>>>(x, cent, betas, out);
}

// round 7
// speedup vs baseline: 3.2830x; 3.2830x over previous
#include <cuda_runtime.h>
#include <math.h>

// out[b,k] = exp(-beta_k * max(||x_b||^2 + ||c_k||^2 - 2 x_b.c_k, 0))
// B=16384, K=4096, D=1024, fp32.
//
// fp32 exp(-t) == exactly 0.0f for t > ~104. Cauchy-Schwarz: d2 >= (||x_b||-||c_k||)^2.
// norms: row norms + per-column interval [lo_k, hi_k] of ||x|| for which the
// element is NOT provably zero. glob: global interval. main: one block per
// (row, 1024-col chunk); block-uniform test of ||x_b|| against the global
// interval -> fast path is a single float4 zero-store per thread (the proven
// fast store shape on this chip); rare interior rows take an exact
// interval-test + fp32 dot + expf path inline. Correct for arbitrary inputs.

#define B_ROWS 16384
#define K_COLS 4096
#define D_DIM  1024
#define THRESH 106.0f

__device__ float g_x2[B_ROWS];
__device__ float g_rx[B_ROWS];
__device__ float g_c2[K_COLS];
__device__ float g_lo[K_COLS];
__device__ float g_hi[K_COLS];
__device__ float g_glo;
__device__ float g_ghi;

// ---------------------------------------------------------------------------
// Kernel 1: row norms. Rows [0,K): centers -> c2, lo, hi. Rows [K,K+B): x -> x2, rx.
// ---------------------------------------------------------------------------
__global__ void __launch_bounds__(256) norms_kernel(const float* __restrict__ x,
                                                    const float* __restrict__ c,
                                                    const float* __restrict__ betas) {
    const int row = blockIdx.x;
    const bool is_center = (row < K_COLS);
    const float* src = is_center ? (c + (size_t)row * D_DIM)
                                 : (x + (size_t)(row - K_COLS) * D_DIM);
    const int tid = threadIdx.x;
    float4 a = reinterpret_cast<const float4*>(src)[tid];
    float s = a.x * a.x + a.y * a.y + a.z * a.z + a.w * a.w;
    #pragma unroll
    for (int o = 16; o > 0; o >>= 1)
        s += __shfl_xor_sync(0xffffffffu, s, o);
    __shared__ float ws[8];
    if ((tid & 31) == 0) ws[tid >> 5] = s;
    __syncthreads();
    if (tid == 0) {
        float t = 0.f;
        #pragma unroll
        for (int i = 0; i < 8; i++) t += ws[i];
        if (is_center) {
            g_c2[row] = t;
            const float beta = betas[row];
            const float sk = sqrtf(t);
            float lo = -INFINITY, hi = INFINITY;
            if (beta > 0.0f && isfinite(sk)) {
                const float rk = sqrtf(THRESH / beta);
                if (isfinite(rk)) { lo = sk - rk; hi = sk + rk; }
            }
            if (!(lo == lo)) lo = -INFINITY;   // NaN -> always-exact interval
            if (!(hi == hi)) hi =  INFINITY;
            g_lo[row] = lo;
            g_hi[row] = hi;
        } else {
            g_x2[row - K_COLS] = t;
            g_rx[row - K_COLS] = sqrtf(t);
        }
    }
}

// ---------------------------------------------------------------------------
// Kernel 2: global interval reduce.
// ---------------------------------------------------------------------------
__global__ void __launch_bounds__(256) glob_kernel() {
    __shared__ float slo[256], shi[256];
    float lo = INFINITY, hi = -INFINITY;
    for (int k = threadIdx.x; k < K_COLS; k += 256) {
        lo = fminf(lo, g_lo[k]);
        hi = fmaxf(hi, g_hi[k]);
    }
    slo[threadIdx.x] = lo;
    shi[threadIdx.x] = hi;
    __syncthreads();
    for (int s2 = 128; s2 > 0; s2 >>= 1) {
        if (threadIdx.x < s2) {
            slo[threadIdx.x] = fminf(slo[threadIdx.x], slo[threadIdx.x + s2]);
            shi[threadIdx.x] = fmaxf(shi[threadIdx.x], shi[threadIdx.x + s2]);
        }
        __syncthreads();
    }
    if (threadIdx.x == 0) { g_glo = slo[0]; g_ghi = shi[0]; }
}

// ---------------------------------------------------------------------------
// Kernel 3: main. Block (chunk, b) owns columns [chunk*1024, chunk*1024+1024)
// of row b. Fast path: ONE float4 store per thread, nothing else.
// ---------------------------------------------------------------------------
__global__ void __launch_bounds__(256) rbf_main(const float* __restrict__ x,
                                                const float* __restrict__ c,
                                                const float* __restrict__ betas,
                                                float* __restrict__ out) {
    const int tid   = threadIdx.x;
    const int b     = blockIdx.y;
    const int kbase = blockIdx.x * 1024 + tid * 4;
    float* __restrict__ optr = out + (size_t)b * K_COLS + kbase;

    const float t = g_rx[b];
    if (t < g_glo || t > g_ghi) {
        // provably-zero row: single streaming store, done. (NaN t falls through)
        *reinterpret_cast<float4*>(optr) = make_float4(0.f, 0.f, 0.f, 0.f);
        return;
    }

    // Exact path (block-uniform branch; rare).
    __shared__ float xs[D_DIM];
    reinterpret_cast<float4*>(xs)[tid] =
        reinterpret_cast<const float4*>(x + (size_t)b * D_DIM)[tid];
    __syncthreads();
    const float sx = g_x2[b];

    const float4 lo4 = *reinterpret_cast<const float4*>(&g_lo[kbase]);
    const float4 hi4 = *reinterpret_cast<const float4*>(&g_hi[kbase]);
    const float4 c24 = *reinterpret_cast<const float4*>(&g_c2[kbase]);
    const float4 bt4 = *reinterpret_cast<const float4*>(&betas[kbase]);
    const float lo_a[4] = {lo4.x, lo4.y, lo4.z, lo4.w};
    const float hi_a[4] = {hi4.x, hi4.y, hi4.z, hi4.w};
    const float c2_a[4] = {c24.x, c24.y, c24.z, c24.w};
    const float bt_a[4] = {bt4.x, bt4.y, bt4.z, bt4.w};

    float o[4];
    #pragma unroll
    for (int q = 0; q < 4; q++) {
        if (t < lo_a[q] || t > hi_a[q]) {
            o[q] = 0.0f;                         // provably underflows
        } else {
            const float* __restrict__ cr = c + (size_t)(kbase + q) * D_DIM;
            float dot = 0.f;
            #pragma unroll 8
            for (int i = 0; i < D_DIM; i++) dot = fmaf(xs[i], cr[i], dot);
            const float d2 = fmaxf(sx + c2_a[q] - 2.0f * dot, 0.0f);
            o[q] = expf(-bt_a[q] * d2);
        }
    }
    *reinterpret_cast<float4*>(optr) = make_float4(o[0], o[1], o[2], o[3]);
}

// ---------------------------------------------------------------------------
extern "C" void kernel_launch(void* const* d_in, const int* in_sizes, int n_in,
                              void* d_out, int out_size) {
    const float* x     = (const float*)d_in[0];
    const float* cent  = (const float*)d_in[1];
    const float* betas = (const float*)d_in[2];
    float* out = (float*)d_out;

    norms_kernel<<<K_COLS + B_ROWS, 256>>>(x, cent, betas);
    glob_kernel<<<1, 256>>>();
    dim3 grid(K_COLS / 1024, B_ROWS);
    rbf_main<<<grid, 256>>>(x, cent, betas, out);
}